// round 1
// baseline (speedup 1.0000x reference)
#include <cuda_runtime.h>

// Problem constants
#define B_ 16
#define T_ 1024
#define D_ 128
#define H_ 1024
#define O_ 64
#define ALPHA 0.1f

#define NCTA 128          // CTAs in persistent kernel; H_/NCTA neurons each
#define HS 8              // neurons per CTA (both layers)
#define NTHR 256          // threads per CTA
#define PSTRIDE 65        // padded partial-buffer row stride (conflict-free)
#define TH_ (T_ * H_)     // batch stride in states arrays
#define TD_ (T_ * D_)     // batch stride in x

// Dynamic SMEM layout (floats):
//   sWrec0[HS*H_] | sWin1[HS*H_] | sWrec1[HS*H_] | sWin0[HS*D_] |
//   sP[128*PSTRIDE] | sV0[128] | sV1[128] | sB0[HS] | sB1[HS]
#define SMEM_FLOATS (3*HS*H_ + HS*D_ + 128*PSTRIDE + 128 + 128 + HS + HS)
#define SMEM_BYTES  (SMEM_FLOATS * 4)

// ---------------------------------------------------------------------------
// Grid-wide barrier (monotonic generation counter; safe across graph replays:
// count always returns to 0, gen keeps incrementing).
// ---------------------------------------------------------------------------
__device__ unsigned int g_bar_count = 0;
__device__ unsigned int g_bar_gen = 0;

__device__ __forceinline__ void grid_barrier() {
    __threadfence();          // make this CTA's stores visible device-wide
    __syncthreads();
    if (threadIdx.x == 0) {
        unsigned int gen = *((volatile unsigned int*)&g_bar_gen);
        if (atomicAdd(&g_bar_count, 1) == NCTA - 1) {
            g_bar_count = 0;
            __threadfence();
            *((volatile unsigned int*)&g_bar_gen) = gen + 1;
        } else {
            while (*((volatile unsigned int*)&g_bar_gen) == gen) { }
        }
        __threadfence();      // acquire side
    }
    __syncthreads();
}

// ---------------------------------------------------------------------------
// FMA helpers
// ---------------------------------------------------------------------------
__device__ __forceinline__ void fma4(float& acc, const float4 a, const float4 w) {
    acc = fmaf(a.x, w.x, acc);
    acc = fmaf(a.y, w.y, acc);
    acc = fmaf(a.z, w.z, acc);
    acc = fmaf(a.w, w.w, acc);
}

// K=1024 segment, one activation read feeds TWO weight matrices (acc1 & acc0).
__device__ __forceinline__ void accum_dual_1024(
    float (&acc1)[4][8], float (&acc0)[4][8],
    const float* __restrict__ actb, int bstride,
    const float* __restrict__ W1s, const float* __restrict__ W0s, int ks)
{
#pragma unroll
    for (int j = 0; j < 4; ++j) {
        const int k = (ks + 64 * j) * 4;
        float4 av[4];
#pragma unroll
        for (int bb = 0; bb < 4; ++bb)
            av[bb] = *(const float4*)(actb + bb * bstride + k);
#pragma unroll
        for (int h = 0; h < 8; ++h) {
            const float4 w1 = *(const float4*)(W1s + h * H_ + k);
            const float4 w0 = *(const float4*)(W0s + h * H_ + k);
#pragma unroll
            for (int bb = 0; bb < 4; ++bb) {
                fma4(acc1[bb][h], av[bb], w1);
                fma4(acc0[bb][h], av[bb], w0);
            }
        }
    }
}

// K=1024 segment, single weight matrix.
__device__ __forceinline__ void accum_single_1024(
    float (&acc)[4][8],
    const float* __restrict__ actb, int bstride,
    const float* __restrict__ Ws, int ks)
{
#pragma unroll
    for (int j = 0; j < 4; ++j) {
        const int k = (ks + 64 * j) * 4;
        float4 av[4];
#pragma unroll
        for (int bb = 0; bb < 4; ++bb)
            av[bb] = *(const float4*)(actb + bb * bstride + k);
#pragma unroll
        for (int h = 0; h < 8; ++h) {
            const float4 w = *(const float4*)(Ws + h * H_ + k);
#pragma unroll
            for (int bb = 0; bb < 4; ++bb)
                fma4(acc[bb][h], av[bb], w);
        }
    }
}

// K=128 segment (x input into layer0); only threads ks<32 participate.
__device__ __forceinline__ void accum_x_128(
    float (&acc)[4][8],
    const float* __restrict__ xb,
    const float* __restrict__ Ws, int ks)
{
    if (ks < 32) {
        const int k = ks * 4;
        float4 av[4];
#pragma unroll
        for (int bb = 0; bb < 4; ++bb)
            av[bb] = *(const float4*)(xb + bb * TD_ + k);
#pragma unroll
        for (int h = 0; h < 8; ++h) {
            const float4 w = *(const float4*)(Ws + h * D_ + k);
#pragma unroll
            for (int bb = 0; bb < 4; ++bb)
                fma4(acc[bb][h], av[bb], w);
        }
    }
}

// Cross-thread (K-split) reduction, leaky-integration state update, tanh, store.
// Thread (bq,ks) holds partials for b=4bq..4bq+3, h=0..7.
// gout points at states + t*H_ + hbase; per-batch stride is TH_.
__device__ __forceinline__ void reduce_update(
    float (&acc)[4][8], float* __restrict__ sP, float* __restrict__ sV,
    const float* __restrict__ sB, float* __restrict__ gout,
    int tid, int bq, int ks)
{
#pragma unroll
    for (int bb = 0; bb < 4; ++bb)
#pragma unroll
        for (int h = 0; h < 8; ++h)
            sP[((bq * 4 + bb) * 8 + h) * PSTRIDE + ks] = acc[bb][h];
    __syncthreads();
    if (tid < 128) {
        const float* p = sP + tid * PSTRIDE;
        float s0 = 0.f, s1 = 0.f, s2 = 0.f, s3 = 0.f;
#pragma unroll
        for (int i = 0; i < 64; i += 4) {
            s0 += p[i]; s1 += p[i + 1]; s2 += p[i + 2]; s3 += p[i + 3];
        }
        const float dot = (s0 + s1) + (s2 + s3);
        const int b = tid >> 3, h = tid & 7;
        const float v = (1.0f - ALPHA) * sV[tid] + ALPHA * (dot + sB[h]);
        sV[tid] = v;
        gout[b * TH_ + h] = tanhf(v);
    }
    __syncthreads();
}

// ---------------------------------------------------------------------------
// Persistent RNN kernel: all T timesteps, weights SMEM-resident.
// ---------------------------------------------------------------------------
extern "C" __global__ void __launch_bounds__(NTHR, 1)
rnn_persistent(const float* __restrict__ x,
               const float* __restrict__ Win0,
               const float* __restrict__ Wrec0,
               const float* __restrict__ bias0,
               const float* __restrict__ Win1,
               const float* __restrict__ Wrec1,
               const float* __restrict__ bias1,
               float* __restrict__ states0,
               float* __restrict__ states1)
{
    extern __shared__ float sm[];
    float* sWrec0 = sm;
    float* sWin1  = sWrec0 + HS * H_;
    float* sWrec1 = sWin1  + HS * H_;
    float* sWin0  = sWrec1 + HS * H_;
    float* sP     = sWin0  + HS * D_;
    float* sV0    = sP  + 128 * PSTRIDE;
    float* sV1    = sV0 + 128;
    float* sB0    = sV1 + 128;
    float* sB1    = sB0 + HS;

    const int tid   = threadIdx.x;
    const int cta   = blockIdx.x;
    const int hbase = cta * HS;
    const int ks    = tid & 63;   // K-split index 0..63 (consecutive in warp)
    const int bq    = tid >> 6;   // batch quad 0..3 -> b = 4bq..4bq+3

    // Prologue: stage this CTA's weight rows into SMEM (rows are contiguous).
    {
        const float4* s; float4* d;
        s = (const float4*)(Wrec0 + hbase * H_); d = (float4*)sWrec0;
        for (int i = tid; i < HS * H_ / 4; i += NTHR) d[i] = s[i];
        s = (const float4*)(Win1 + hbase * H_);  d = (float4*)sWin1;
        for (int i = tid; i < HS * H_ / 4; i += NTHR) d[i] = s[i];
        s = (const float4*)(Wrec1 + hbase * H_); d = (float4*)sWrec1;
        for (int i = tid; i < HS * H_ / 4; i += NTHR) d[i] = s[i];
        s = (const float4*)(Win0 + hbase * D_);  d = (float4*)sWin0;
        for (int i = tid; i < HS * D_ / 4; i += NTHR) d[i] = s[i];
        if (tid < HS) { sB0[tid] = bias0[hbase + tid]; sB1[tid] = bias1[hbase + tid]; }
        if (tid < 128) { sV0[tid] = 0.f; sV1[tid] = 0.f; }
    }
    __syncthreads();

    // Pre-phase: layer0(t=0) = alpha*(x_0 @ Win0^T + b0); recurrent term is 0.
    {
        float a0[4][8];
#pragma unroll
        for (int bb = 0; bb < 4; ++bb)
#pragma unroll
            for (int h = 0; h < 8; ++h) a0[bb][h] = 0.f;
        accum_x_128(a0, x + (bq * 4) * TD_ /* t=0 */, sWin0, ks);
        reduce_update(a0, sP, sV0, sB0, states0 + hbase /* t=0 */, tid, bq, ks);
        grid_barrier();
    }

    // Main loop: phase t computes layer1(t) and layer0(t+1).
    for (int t = 0; t < T_; ++t) {
        const bool doL0 = (t < T_ - 1);
        float a1[4][8], a0[4][8];
#pragma unroll
        for (int bb = 0; bb < 4; ++bb)
#pragma unroll
            for (int h = 0; h < 8; ++h) { a1[bb][h] = 0.f; a0[bb][h] = 0.f; }

        const float* fr0b = states0 + (bq * 4) * TH_ + t * H_;
        if (doL0) {
            // fr0(t) feeds both Win1 (layer1) and Wrec0 (layer0 @ t+1)
            accum_dual_1024(a1, a0, fr0b, TH_, sWin1, sWrec0, ks);
        } else {
            accum_single_1024(a1, fr0b, TH_, sWin1, ks);
        }
        if (t > 0) {
            const float* fr1b = states1 + (bq * 4) * TH_ + (t - 1) * H_;
            accum_single_1024(a1, fr1b, TH_, sWrec1, ks);
        }
        if (doL0) {
            accum_x_128(a0, x + (bq * 4) * TD_ + (t + 1) * D_, sWin0, ks);
        }

        reduce_update(a1, sP, sV1, sB1, states1 + t * H_ + hbase, tid, bq, ks);
        if (doL0) {
            reduce_update(a0, sP, sV0, sB0, states0 + (t + 1) * H_ + hbase, tid, bq, ks);
            grid_barrier();
        }
    }
}

// ---------------------------------------------------------------------------
// Readout GEMM: C[16384,64] = S[16384,1024] @ W^T[1024,64] + b
// 64x64 tile per CTA, 4x4 register micro-tile per thread, BK=32.
// ---------------------------------------------------------------------------
extern "C" __global__ void __launch_bounds__(256)
out_gemm(const float* __restrict__ S,
         const float* __restrict__ W,     // [O_][H_]
         const float* __restrict__ bo,    // [O_]
         float* __restrict__ C)           // [B_*T_][O_]
{
    __shared__ float sS[32][68];   // [k][row], padded
    __shared__ float sW[32][64];   // [k][o]

    const int tid = threadIdx.x;
    const int r0  = blockIdx.x * 64;
    const int tr  = tid & 15;
    const int tc  = tid >> 4;

    float acc[4][4];
#pragma unroll
    for (int i = 0; i < 4; ++i)
#pragma unroll
        for (int j = 0; j < 4; ++j) acc[i][j] = 0.f;

    for (int kb = 0; kb < H_; kb += 32) {
#pragma unroll
        for (int i = 0; i < 2; ++i) {
            int f = tid + i * 256;              // 512 float4 total
            int row = f >> 3, kq = f & 7;
            float4 v = *(const float4*)(S + (r0 + row) * H_ + kb + kq * 4);
            sS[kq * 4 + 0][row] = v.x; sS[kq * 4 + 1][row] = v.y;
            sS[kq * 4 + 2][row] = v.z; sS[kq * 4 + 3][row] = v.w;
        }
#pragma unroll
        for (int i = 0; i < 2; ++i) {
            int f = tid + i * 256;
            int o = f >> 3, kq = f & 7;
            float4 v = *(const float4*)(W + o * H_ + kb + kq * 4);
            sW[kq * 4 + 0][o] = v.x; sW[kq * 4 + 1][o] = v.y;
            sW[kq * 4 + 2][o] = v.z; sW[kq * 4 + 3][o] = v.w;
        }
        __syncthreads();
#pragma unroll
        for (int k = 0; k < 32; ++k) {
            const float4 av = *(const float4*)&sS[k][tr * 4];
            const float4 wv = *(const float4*)&sW[k][tc * 4];
            const float a_[4] = { av.x, av.y, av.z, av.w };
            const float w_[4] = { wv.x, wv.y, wv.z, wv.w };
#pragma unroll
            for (int i = 0; i < 4; ++i)
#pragma unroll
                for (int j = 0; j < 4; ++j)
                    acc[i][j] = fmaf(a_[i], w_[j], acc[i][j]);
        }
        __syncthreads();
    }

#pragma unroll
    for (int i = 0; i < 4; ++i) {
        float4 o4;
        o4.x = acc[i][0] + bo[tc * 4 + 0];
        o4.y = acc[i][1] + bo[tc * 4 + 1];
        o4.z = acc[i][2] + bo[tc * 4 + 2];
        o4.w = acc[i][3] + bo[tc * 4 + 3];
        *(float4*)&C[(r0 + tr * 4 + i) * O_ + tc * 4] = o4;
    }
}

// ---------------------------------------------------------------------------
// kernel_launch
// Inputs (metadata order): x, W_in0, W_rec0, b0, W_in1, W_rec1, b1, W_out, b_out
// Output: concat(output[B,T,O], states0[B,T,H], states1[B,T,H]) as float32.
// ---------------------------------------------------------------------------
extern "C" void kernel_launch(void* const* d_in, const int* in_sizes, int n_in,
                              void* d_out, int out_size) {
    const float* x     = (const float*)d_in[0];
    const float* Win0  = (const float*)d_in[1];
    const float* Wrec0 = (const float*)d_in[2];
    const float* b0    = (const float*)d_in[3];
    const float* Win1  = (const float*)d_in[4];
    const float* Wrec1 = (const float*)d_in[5];
    const float* b1    = (const float*)d_in[6];
    const float* Wout  = (const float*)d_in[7];
    const float* bout  = (const float*)d_in[8];

    float* out     = (float*)d_out;
    float* output  = out;
    float* states0 = out + (size_t)B_ * T_ * O_;
    float* states1 = states0 + (size_t)B_ * T_ * H_;

    cudaFuncSetAttribute(rnn_persistent,
                         cudaFuncAttributeMaxDynamicSharedMemorySize, SMEM_BYTES);

    rnn_persistent<<<NCTA, NTHR, SMEM_BYTES>>>(
        x, Win0, Wrec0, b0, Win1, Wrec1, b1, states0, states1);

    out_gemm<<<(B_ * T_) / 64, 256>>>(states1, Wout, bout, output);
}

// round 8
// speedup vs baseline: 1.0635x; 1.0635x over previous
#include <cuda_runtime.h>

// Problem constants
#define B_ 16
#define T_ 1024
#define D_ 128
#define H_ 1024
#define O_ 64
#define ALPHA 0.1f

#define NCTA 128          // CTAs in persistent kernel; H_/NCTA neurons each
#define HS 8              // neurons per CTA (both layers)
#define NTHR 256          // threads per CTA
#define PS 68             // padded partial-buffer row stride (16B-aligned, conflict-free)
#define TH_ (T_ * H_)     // batch stride in states arrays
#define TD_ (T_ * D_)     // batch stride in x

// Dynamic SMEM layout (floats):
//   sWrec0[HS*H_] | sWin1[HS*H_] | sWrec1[HS*H_] | sWin0[HS*D_] |
//   sP[256*PS] | sV0[128] | sV1[128] | sB0[HS] | sB1[HS]
#define SMEM_FLOATS (3*HS*H_ + HS*D_ + 256*PS + 128 + 128 + HS + HS)
#define SMEM_BYTES  (SMEM_FLOATS * 4)

typedef unsigned long long u64;

// ---------------------------------------------------------------------------
// Packed fp32x2 FMA (sm_100+; ptxas never emits this — PTX only).
// d (2 packed fp32 accumulators) += a * b, lanewise. Doubles fp32 MAC
// throughput per issue slot vs scalar FFMA.
// ---------------------------------------------------------------------------
__device__ __forceinline__ void ffma2(u64& d, u64 a, u64 b) {
    asm volatile("fma.rn.f32x2 %0, %1, %2, %0;" : "+l"(d) : "l"(a), "l"(b));
}
__device__ __forceinline__ float hadd2(u64 a) {
    float lo, hi;
    asm("mov.b64 {%0, %1}, %2;" : "=f"(lo), "=f"(hi) : "l"(a));
    return lo + hi;
}

// ---------------------------------------------------------------------------
// Grid-wide barrier: monotonic counter. Arrival = red.release (fire & forget,
// no serialized ATOMG round-trips); wait = acquire-load poll against a growing
// target, followed by a full gpu-scope fence so later WEAK loads by ALL
// threads of the CTA observe peer-CTA writes (same strength as the pattern
// measured working in R1). g_count is zeroed by bar_init once per replay.
// ---------------------------------------------------------------------------
__device__ unsigned int g_count;

extern "C" __global__ void bar_init() { g_count = 0; }

__device__ __forceinline__ void grid_barrier(unsigned int target) {
    __syncthreads();                       // CTA stores ordered before release
    if (threadIdx.x == 0) {
        asm volatile("red.release.gpu.global.add.u32 [%0], 1;"
                     :: "l"(&g_count) : "memory");
        unsigned int v;
        do {
            asm volatile("ld.acquire.gpu.global.u32 %0, [%1];"
                         : "=r"(v) : "l"(&g_count) : "memory");
        } while (v < target);
        __threadfence();                   // belt-and-suspenders acquire fence
    }
    __syncthreads();                       // acquire visible to whole CTA
}

// ---------------------------------------------------------------------------
// GEMM accumulation pieces. Thread (bq, ks): bq=tid>>6 (4 batches each),
// ks=tid&63 (K-split). Accumulators are packed even/odd-k fp32 pairs.
// ---------------------------------------------------------------------------

// K=1024, one activation read feeds TWO weight matrices (acc1 & acc0).
__device__ __forceinline__ void accum_dual_1024(
    u64 (&acc1)[4][8], u64 (&acc0)[4][8],
    const float* __restrict__ actb, int bstride,
    const float* __restrict__ W1s, const float* __restrict__ W0s, int ks)
{
#pragma unroll
    for (int j = 0; j < 4; ++j) {
        const int k = (ks + 64 * j) * 4;
        ulonglong2 av[4];
#pragma unroll
        for (int bb = 0; bb < 4; ++bb)
            av[bb] = *(const ulonglong2*)(actb + bb * bstride + k);
#pragma unroll
        for (int h = 0; h < 8; ++h) {
            const ulonglong2 w1 = *(const ulonglong2*)(W1s + h * H_ + k);
            const ulonglong2 w0 = *(const ulonglong2*)(W0s + h * H_ + k);
#pragma unroll
            for (int bb = 0; bb < 4; ++bb) {
                ffma2(acc1[bb][h], av[bb].x, w1.x);
                ffma2(acc1[bb][h], av[bb].y, w1.y);
                ffma2(acc0[bb][h], av[bb].x, w0.x);
                ffma2(acc0[bb][h], av[bb].y, w0.y);
            }
        }
    }
}

// K=1024, single weight matrix.
__device__ __forceinline__ void accum_single_1024(
    u64 (&acc)[4][8],
    const float* __restrict__ actb, int bstride,
    const float* __restrict__ Ws, int ks)
{
#pragma unroll
    for (int j = 0; j < 4; ++j) {
        const int k = (ks + 64 * j) * 4;
        ulonglong2 av[4];
#pragma unroll
        for (int bb = 0; bb < 4; ++bb)
            av[bb] = *(const ulonglong2*)(actb + bb * bstride + k);
#pragma unroll
        for (int h = 0; h < 8; ++h) {
            const ulonglong2 w = *(const ulonglong2*)(Ws + h * H_ + k);
#pragma unroll
            for (int bb = 0; bb < 4; ++bb) {
                ffma2(acc[bb][h], av[bb].x, w.x);
                ffma2(acc[bb][h], av[bb].y, w.y);
            }
        }
    }
}

// K=128 (x input into layer0); only threads ks<32 participate.
__device__ __forceinline__ void accum_x_128(
    u64 (&acc)[4][8],
    const float* __restrict__ xb,
    const float* __restrict__ Ws, int ks)
{
    if (ks < 32) {
        const int k = ks * 4;
        ulonglong2 av[4];
#pragma unroll
        for (int bb = 0; bb < 4; ++bb)
            av[bb] = *(const ulonglong2*)(xb + bb * TD_ + k);
#pragma unroll
        for (int h = 0; h < 8; ++h) {
            const ulonglong2 w = *(const ulonglong2*)(Ws + h * D_ + k);
#pragma unroll
            for (int bb = 0; bb < 4; ++bb) {
                ffma2(acc[bb][h], av[bb].x, w.x);
                ffma2(acc[bb][h], av[bb].y, w.y);
            }
        }
    }
}

// Merged cross-thread reduction for BOTH layers: one __syncthreads, all 256
// threads reduce (tid 0..127 -> layer1 row, tid 128..255 -> layer0 row).
// sP rows: [0,128) layer1, [128,256) layer0; row = b*8+h, col = ks.
__device__ __forceinline__ void reduce_merged(
    u64 (&a1)[4][8], u64 (&a0)[4][8], bool do1, bool do0,
    float* __restrict__ sP, float* __restrict__ sV0, float* __restrict__ sV1,
    const float* __restrict__ sB0, const float* __restrict__ sB1,
    float* __restrict__ g1, float* __restrict__ g0,
    int tid, int bq, int ks)
{
#pragma unroll
    for (int bb = 0; bb < 4; ++bb)
#pragma unroll
        for (int h = 0; h < 8; ++h) {
            const int row = (bq * 4 + bb) * 8 + h;
            sP[row * PS + ks]         = hadd2(a1[bb][h]);
            sP[(128 + row) * PS + ks] = hadd2(a0[bb][h]);
        }
    __syncthreads();

    const int layer0_side = tid >> 7;       // 0: layer1 rows, 1: layer0 rows
    const int idx = tid & 127;
    const bool active = layer0_side ? do0 : do1;
    if (active) {
        const float4* p = (const float4*)(sP + tid * PS);
        float4 s = p[0];
#pragma unroll
        for (int i = 1; i < 16; ++i) {
            const float4 q = p[i];
            s.x += q.x; s.y += q.y; s.z += q.z; s.w += q.w;
        }
        const float dot = (s.x + s.y) + (s.z + s.w);
        const int b = idx >> 3, h = idx & 7;
        float* sV = layer0_side ? sV0 : sV1;
        const float bias = layer0_side ? sB0[h] : sB1[h];
        const float v = (1.0f - ALPHA) * sV[idx] + ALPHA * (dot + bias);
        sV[idx] = v;
        float* g = layer0_side ? g0 : g1;
        g[b * TH_ + h] = tanhf(v);
    }
    // No trailing sync: the grid_barrier (or kernel end) orders reuse of sP.
}

// ---------------------------------------------------------------------------
// Persistent RNN kernel: all T timesteps, weights SMEM-resident.
// Phase t computes layer1(t) and layer0(t+1); one grid barrier per phase.
// ---------------------------------------------------------------------------
extern "C" __global__ void __launch_bounds__(NTHR, 1)
rnn_persistent(const float* __restrict__ x,
               const float* __restrict__ Win0,
               const float* __restrict__ Wrec0,
               const float* __restrict__ bias0,
               const float* __restrict__ Win1,
               const float* __restrict__ Wrec1,
               const float* __restrict__ bias1,
               float* __restrict__ states0,
               float* __restrict__ states1)
{
    extern __shared__ float sm[];
    float* sWrec0 = sm;
    float* sWin1  = sWrec0 + HS * H_;
    float* sWrec1 = sWin1  + HS * H_;
    float* sWin0  = sWrec1 + HS * H_;
    float* sP     = sWin0  + HS * D_;
    float* sV0    = sP  + 256 * PS;
    float* sV1    = sV0 + 128;
    float* sB0    = sV1 + 128;
    float* sB1    = sB0 + HS;

    const int tid   = threadIdx.x;
    const int cta   = blockIdx.x;
    const int hbase = cta * HS;
    const int ks    = tid & 63;   // K-split index 0..63
    const int bq    = tid >> 6;   // batch quad 0..3

    // Prologue: stage this CTA's weight rows into SMEM.
    {
        const float4* s; float4* d;
        s = (const float4*)(Wrec0 + hbase * H_); d = (float4*)sWrec0;
        for (int i = tid; i < HS * H_ / 4; i += NTHR) d[i] = s[i];
        s = (const float4*)(Win1 + hbase * H_);  d = (float4*)sWin1;
        for (int i = tid; i < HS * H_ / 4; i += NTHR) d[i] = s[i];
        s = (const float4*)(Wrec1 + hbase * H_); d = (float4*)sWrec1;
        for (int i = tid; i < HS * H_ / 4; i += NTHR) d[i] = s[i];
        s = (const float4*)(Win0 + hbase * D_);  d = (float4*)sWin0;
        for (int i = tid; i < HS * D_ / 4; i += NTHR) d[i] = s[i];
        if (tid < HS) { sB0[tid] = bias0[hbase + tid]; sB1[tid] = bias1[hbase + tid]; }
        if (tid < 128) { sV0[tid] = 0.f; sV1[tid] = 0.f; }
    }
    __syncthreads();

    unsigned int bar_target = NCTA;

    // Pre-phase: layer0(t=0) = alpha*(x_0 @ Win0^T + b0); recurrent term 0.
    {
        u64 a1[4][8], a0[4][8];
#pragma unroll
        for (int bb = 0; bb < 4; ++bb)
#pragma unroll
            for (int h = 0; h < 8; ++h) { a1[bb][h] = 0ull; a0[bb][h] = 0ull; }
        accum_x_128(a0, x + (bq * 4) * TD_ /* t=0 */, sWin0, ks);
        reduce_merged(a1, a0, false, true, sP, sV0, sV1, sB0, sB1,
                      states1 /*unused*/, states0 + hbase, tid, bq, ks);
        grid_barrier(bar_target); bar_target += NCTA;
    }

    // Main loop.
    for (int t = 0; t < T_; ++t) {
        const bool doL0 = (t < T_ - 1);
        u64 a1[4][8], a0[4][8];
#pragma unroll
        for (int bb = 0; bb < 4; ++bb)
#pragma unroll
            for (int h = 0; h < 8; ++h) { a1[bb][h] = 0ull; a0[bb][h] = 0ull; }

        const float* fr0b = states0 + (bq * 4) * TH_ + t * H_;
        if (doL0) {
            // fr0(t) feeds both Win1 (layer1 @ t) and Wrec0 (layer0 @ t+1)
            accum_dual_1024(a1, a0, fr0b, TH_, sWin1, sWrec0, ks);
        } else {
            accum_single_1024(a1, fr0b, TH_, sWin1, ks);
        }
        if (t > 0) {
            const float* fr1b = states1 + (bq * 4) * TH_ + (t - 1) * H_;
            accum_single_1024(a1, fr1b, TH_, sWrec1, ks);
        }
        if (doL0) {
            accum_x_128(a0, x + (bq * 4) * TD_ + (t + 1) * D_, sWin0, ks);
        }

        reduce_merged(a1, a0, true, doL0, sP, sV0, sV1, sB0, sB1,
                      states1 + t * H_ + hbase,
                      states0 + (t + 1) * H_ + hbase, tid, bq, ks);
        if (doL0) { grid_barrier(bar_target); bar_target += NCTA; }
    }
}

// ---------------------------------------------------------------------------
// Readout GEMM: C[16384,64] = S[16384,1024] @ W^T[1024,64] + b
// ---------------------------------------------------------------------------
extern "C" __global__ void __launch_bounds__(256)
out_gemm(const float* __restrict__ S,
         const float* __restrict__ W,     // [O_][H_]
         const float* __restrict__ bo,    // [O_]
         float* __restrict__ C)           // [B_*T_][O_]
{
    __shared__ float sS[32][68];   // [k][row], padded
    __shared__ float sW[32][64];   // [k][o]

    const int tid = threadIdx.x;
    const int r0  = blockIdx.x * 64;
    const int tr  = tid & 15;
    const int tc  = tid >> 4;

    float acc[4][4];
#pragma unroll
    for (int i = 0; i < 4; ++i)
#pragma unroll
        for (int j = 0; j < 4; ++j) acc[i][j] = 0.f;

    for (int kb = 0; kb < H_; kb += 32) {
#pragma unroll
        for (int i = 0; i < 2; ++i) {
            int f = tid + i * 256;
            int row = f >> 3, kq = f & 7;
            float4 v = *(const float4*)(S + (r0 + row) * H_ + kb + kq * 4);
            sS[kq * 4 + 0][row] = v.x; sS[kq * 4 + 1][row] = v.y;
            sS[kq * 4 + 2][row] = v.z; sS[kq * 4 + 3][row] = v.w;
        }
#pragma unroll
        for (int i = 0; i < 2; ++i) {
            int f = tid + i * 256;
            int o = f >> 3, kq = f & 7;
            float4 v = *(const float4*)(W + o * H_ + kb + kq * 4);
            sW[kq * 4 + 0][o] = v.x; sW[kq * 4 + 1][o] = v.y;
            sW[kq * 4 + 2][o] = v.z; sW[kq * 4 + 3][o] = v.w;
        }
        __syncthreads();
#pragma unroll
        for (int k = 0; k < 32; ++k) {
            const float4 av = *(const float4*)&sS[k][tr * 4];
            const float4 wv = *(const float4*)&sW[k][tc * 4];
            const float a_[4] = { av.x, av.y, av.z, av.w };
            const float w_[4] = { wv.x, wv.y, wv.z, wv.w };
#pragma unroll
            for (int i = 0; i < 4; ++i)
#pragma unroll
                for (int j = 0; j < 4; ++j)
                    acc[i][j] = fmaf(a_[i], w_[j], acc[i][j]);
        }
        __syncthreads();
    }

#pragma unroll
    for (int i = 0; i < 4; ++i) {
        float4 o4;
        o4.x = acc[i][0] + bo[tc * 4 + 0];
        o4.y = acc[i][1] + bo[tc * 4 + 1];
        o4.z = acc[i][2] + bo[tc * 4 + 2];
        o4.w = acc[i][3] + bo[tc * 4 + 3];
        *(float4*)&C[(r0 + tr * 4 + i) * O_ + tc * 4] = o4;
    }
}

// ---------------------------------------------------------------------------
// kernel_launch
// Inputs: x, W_in0, W_rec0, b0, W_in1, W_rec1, b1, W_out, b_out
// Output: concat(output[B,T,O], states0[B,T,H], states1[B,T,H]) as float32.
// ---------------------------------------------------------------------------
extern "C" void kernel_launch(void* const* d_in, const int* in_sizes, int n_in,
                              void* d_out, int out_size) {
    const float* x     = (const float*)d_in[0];
    const float* Win0  = (const float*)d_in[1];
    const float* Wrec0 = (const float*)d_in[2];
    const float* b0    = (const float*)d_in[3];
    const float* Win1  = (const float*)d_in[4];
    const float* Wrec1 = (const float*)d_in[5];
    const float* b1    = (const float*)d_in[6];
    const float* Wout  = (const float*)d_in[7];
    const float* bout  = (const float*)d_in[8];

    float* out     = (float*)d_out;
    float* output  = out;
    float* states0 = out + (size_t)B_ * T_ * O_;
    float* states1 = states0 + (size_t)B_ * T_ * H_;

    cudaFuncSetAttribute(rnn_persistent,
                         cudaFuncAttributeMaxDynamicSharedMemorySize, SMEM_BYTES);

    bar_init<<<1, 1>>>();
    rnn_persistent<<<NCTA, NTHR, SMEM_BYTES>>>(
        x, Win0, Wrec0, b0, Win1, Wrec1, b1, states0, states1);

    out_gemm<<<(B_ * T_) / 64, 256>>>(states1, Wout, bout, output);
}